// round 7
// baseline (speedup 1.0000x reference)
#include <cuda_runtime.h>
#include <cuda_bf16.h>
#include <cstdint>

#define D_      128
#define NVARS   50000
#define V2_     100000
#define NCL     200000
#define NTOTAL  300000
#define NROUNDS 16

// ---------------- persistent scratch ---------------------------------------
__device__ float g_h[(size_t)NTOTAL * D_];
__device__ float g_c[(size_t)NTOTAL * D_];
__device__ float g_msg[(size_t)NCL * D_];
__device__ float g_t0[(size_t)NCL * D_];
__device__ float g_t1[(size_t)NCL * D_];
__device__ float g_gates[(size_t)NCL * 4 * D_];

// ---------------- bf16 split helpers ---------------------------------------
__device__ __forceinline__ void cvt2(float x, float y, uint32_t& hi, uint32_t& lo) {
    __nv_bfloat16 hx = __float2bfloat16_rn(x);
    __nv_bfloat16 hy = __float2bfloat16_rn(y);
    __nv_bfloat162 hp = __halves2bfloat162(hx, hy);
    hi = *(uint32_t*)&hp;
    __nv_bfloat16 lx = __float2bfloat16_rn(x - __bfloat162float(hx));
    __nv_bfloat16 ly = __float2bfloat16_rn(y - __bfloat162float(hy));
    __nv_bfloat162 lp = __halves2bfloat162(lx, ly);
    lo = *(uint32_t*)&lp;
}

__device__ __forceinline__ void mma_bf16(float* d, const uint32_t* a, uint32_t b0, uint32_t b1) {
    asm volatile(
        "mma.sync.aligned.m16n8k16.row.col.f32.bf16.bf16.f32 "
        "{%0,%1,%2,%3}, {%4,%5,%6,%7}, {%8,%9}, {%0,%1,%2,%3};\n"
        : "+f"(d[0]), "+f"(d[1]), "+f"(d[2]), "+f"(d[3])
        : "r"(a[0]), "r"(a[1]), "r"(a[2]), "r"(a[3]), "r"(b0), "r"(b1));
}

// ---------------- tensor GEMM (mma.sync, bf16 3-pass split) -----------------
// C[M, bcol:bcol+128] = sum_t A_t[M,128] @ B_t[:, koff:koff+128]^T + bias(s)
#define TSTR 68   // u32 row stride of a 128x(64 u32) tile, +4 pad

struct TcArgs {
    const float* A[3];
    const float* B[3];
    int ldb[3];
    int koff[3];
    int negflip[3];
    int nTerms;
    const float* bias0;
    const float* bias1;
    float* C;
    int M, N;
    int relu;
};

#define SMEM_TC_BYTES (4 * 128 * TSTR * 4)

__global__ __launch_bounds__(256) void tc_gemm(TcArgs a) {
    extern __shared__ uint32_t sm[];
    uint32_t* Ahi = sm;
    uint32_t* Alo = sm + 128 * TSTR;
    uint32_t* Bhi = sm + 2 * 128 * TSTR;
    uint32_t* Blo = sm + 3 * 128 * TSTR;

    const int tid  = threadIdx.x;
    const int wid  = tid >> 5;
    const int lane = tid & 31;
    const int g    = lane >> 2;
    const int t    = lane & 3;
    const int wm   = (wid >> 1) * 32;   // 4 warp-rows
    const int wn   = (wid & 1) * 64;    // 2 warp-cols
    const int brow = blockIdx.x << 7;
    const int bcol = blockIdx.y << 7;

    float acc[2][8][4];
#pragma unroll
    for (int mf = 0; mf < 2; ++mf)
#pragma unroll
        for (int nf = 0; nf < 8; ++nf)
#pragma unroll
            for (int k = 0; k < 4; ++k) acc[mf][nf][k] = 0.f;

    for (int term = 0; term < a.nTerms; ++term) {
        if (term) __syncthreads();     // prior compute done before overwrite
        // ---- fill A hi/lo tile ----
        const float* Ag = a.A[term];
        const int nflip = a.negflip[term];
#pragma unroll 4
        for (int i = 0; i < 16; ++i) {
            int f = i * 256 + tid;
            int r = f >> 5, c4 = f & 31;
            int gr = brow + r;
            float4 v = make_float4(0.f, 0.f, 0.f, 0.f);
            if (gr < a.M) {
                int src = gr;
                if (nflip) src = (src < NVARS) ? src + NVARS : src - NVARS;
                v = *(const float4*)(Ag + (size_t)src * D_ + c4 * 4);
            }
            uint32_t h0, l0, h1, l1;
            cvt2(v.x, v.y, h0, l0);
            cvt2(v.z, v.w, h1, l1);
            *(uint2*)(Ahi + r * TSTR + c4 * 2) = make_uint2(h0, h1);
            *(uint2*)(Alo + r * TSTR + c4 * 2) = make_uint2(l0, l1);
        }
        // ---- fill B hi/lo tile ----
        const float* Bg = a.B[term];
        const int ldb = a.ldb[term];
        const int ko  = a.koff[term];
#pragma unroll 4
        for (int i = 0; i < 16; ++i) {
            int f = i * 256 + tid;
            int r = f >> 5, c4 = f & 31;
            int nrow = bcol + r;
            float4 v = *(const float4*)(Bg + (size_t)nrow * ldb + ko + c4 * 4);
            uint32_t h0, l0, h1, l1;
            cvt2(v.x, v.y, h0, l0);
            cvt2(v.z, v.w, h1, l1);
            *(uint2*)(Bhi + r * TSTR + c4 * 2) = make_uint2(h0, h1);
            *(uint2*)(Blo + r * TSTR + c4 * 2) = make_uint2(l0, l1);
        }
        __syncthreads();

        // ---- compute: 8 k-steps of k16 ----
#pragma unroll
        for (int ks = 0; ks < 8; ++ks) {
            const int c0 = ks * 8 + t;
            uint32_t ah[2][4], al[2][4];
#pragma unroll
            for (int mf = 0; mf < 2; ++mf) {
                const int r = wm + mf * 16 + g;
                const uint32_t* p = Ahi + r * TSTR + c0;
                ah[mf][0] = p[0];
                ah[mf][1] = p[8 * TSTR];
                ah[mf][2] = p[4];
                ah[mf][3] = p[8 * TSTR + 4];
                const uint32_t* q = Alo + r * TSTR + c0;
                al[mf][0] = q[0];
                al[mf][1] = q[8 * TSTR];
                al[mf][2] = q[4];
                al[mf][3] = q[8 * TSTR + 4];
            }
#pragma unroll
            for (int nf = 0; nf < 8; ++nf) {
                const int nr = wn + nf * 8 + g;
                const uint32_t* pb = Bhi + nr * TSTR + c0;
                uint32_t bh0 = pb[0], bh1 = pb[4];
                const uint32_t* qb = Blo + nr * TSTR + c0;
                uint32_t bl0 = qb[0], bl1 = qb[4];
#pragma unroll
                for (int mf = 0; mf < 2; ++mf) {
                    mma_bf16(acc[mf][nf], ah[mf], bh0, bh1);
                    mma_bf16(acc[mf][nf], ah[mf], bl0, bl1);
                    mma_bf16(acc[mf][nf], al[mf], bh0, bh1);
                }
            }
        }
    }

    // ---- epilogue: bias (+bias1) + optional relu, direct STG ----
#pragma unroll
    for (int nf = 0; nf < 8; ++nf) {
        const int col = bcol + wn + nf * 8 + 2 * t;
        float b0v = a.bias0[col], b1v = a.bias0[col + 1];
        if (a.bias1) { b0v += a.bias1[col]; b1v += a.bias1[col + 1]; }
#pragma unroll
        for (int mf = 0; mf < 2; ++mf) {
            const int row = brow + wm + mf * 16 + g;
            float x0 = acc[mf][nf][0] + b0v;
            float x1 = acc[mf][nf][1] + b1v;
            float x2 = acc[mf][nf][2] + b0v;
            float x3 = acc[mf][nf][3] + b1v;
            if (a.relu) {
                x0 = fmaxf(x0, 0.f); x1 = fmaxf(x1, 0.f);
                x2 = fmaxf(x2, 0.f); x3 = fmaxf(x3, 0.f);
            }
            if (row < a.M) {
                float2 v = make_float2(x0, x1);
                *(float2*)(a.C + (size_t)row * a.N + col) = v;
            }
            if (row + 8 < a.M) {
                float2 v = make_float2(x2, x3);
                *(float2*)(a.C + (size_t)(row + 8) * a.N + col) = v;
            }
        }
    }
}

// ---------------- edge scatter-add -----------------------------------------
__global__ void scatter_kernel(const float* __restrict__ rows,
                               const int* __restrict__ gidx,
                               const int* __restrict__ sidx,
                               int E, float* __restrict__ out) {
    int e = blockIdx.x * 8 + threadIdx.y;
    if (e >= E) return;
    int s = gidx[e];
    int d = sidx[e];
    float4 v = *(const float4*)(rows + (size_t)s * D_ + threadIdx.x * 4);
    float* p = out + (size_t)d * D_ + threadIdx.x * 4;
    asm volatile("red.global.add.v4.f32 [%0], {%1, %2, %3, %4};"
                 :: "l"(p), "f"(v.x), "f"(v.y), "f"(v.z), "f"(v.w)
                 : "memory");
}

// ---------------- elementwise ----------------------------------------------
__device__ __forceinline__ float sigf(float x) { return 1.f / (1.f + expf(-x)); }

__global__ void lstm_kernel(const float* __restrict__ gates,
                            float* __restrict__ h, float* __restrict__ c, int M) {
    size_t idx = (size_t)blockIdx.x * blockDim.x + threadIdx.x;
    if (idx >= (size_t)M * 32) return;
    size_t r = idx >> 5;
    int q = (int)(idx & 31) * 4;
    const float* gb = gates + r * 512;
    float4 gi = *(const float4*)(gb + q);
    float4 gf = *(const float4*)(gb + 128 + q);
    float4 gg = *(const float4*)(gb + 256 + q);
    float4 go = *(const float4*)(gb + 384 + q);
    float4 cc = *(const float4*)(c + r * D_ + q);
    float4 c2, hh;
    c2.x = sigf(gf.x) * cc.x + sigf(gi.x) * tanhf(gg.x); hh.x = sigf(go.x) * tanhf(c2.x);
    c2.y = sigf(gf.y) * cc.y + sigf(gi.y) * tanhf(gg.y); hh.y = sigf(go.y) * tanhf(c2.y);
    c2.z = sigf(gf.z) * cc.z + sigf(gi.z) * tanhf(gg.z); hh.z = sigf(go.z) * tanhf(c2.z);
    c2.w = sigf(gf.w) * cc.w + sigf(gi.w) * tanhf(gg.w); hh.w = sigf(go.w) * tanhf(c2.w);
    *(float4*)(c + r * D_ + q) = c2;
    *(float4*)(h + r * D_ + q) = hh;
}

__global__ void init_kernel(const float* __restrict__ lw, const float* __restrict__ lb,
                            const float* __restrict__ cw, const float* __restrict__ cb,
                            float* __restrict__ h) {
    int d = threadIdx.x;
    size_t row = blockIdx.x;
    float v = (row < V2_) ? (lw[d] + lb[d]) : (cw[d] + cb[d]);
    h[row * D_ + d] = v;
}

__global__ void zero_kernel(float4* __restrict__ p, size_t n4) {
    size_t i = (size_t)blockIdx.x * blockDim.x + threadIdx.x;
    if (i < n4) p[i] = make_float4(0.f, 0.f, 0.f, 0.f);
}

__global__ void copy_kernel(const float4* __restrict__ src, float4* __restrict__ dst, size_t n4) {
    size_t i = (size_t)blockIdx.x * blockDim.x + threadIdx.x;
    if (i < n4) dst[i] = src[i];
}

// ---------------- host wrappers --------------------------------------------
static void tc_launch(const TcArgs& a) {
    dim3 grid((a.M + 127) >> 7, a.N >> 7);
    tc_gemm<<<grid, 256, SMEM_TC_BYTES>>>(a);
}

static void tc1(const float* A, const float* B, const float* bias,
                float* C, int M, int N, int relu) {
    TcArgs a = {};
    a.A[0] = A; a.B[0] = B; a.ldb[0] = 128; a.koff[0] = 0; a.negflip[0] = 0;
    a.nTerms = 1; a.bias0 = bias; a.bias1 = nullptr;
    a.C = C; a.M = M; a.N = N; a.relu = relu;
    tc_launch(a);
}

static void tc2(const float* A0, const float* B0,
                const float* A1, const float* B1,
                const float* bias0, const float* bias1,
                float* C, int M, int N) {
    TcArgs a = {};
    a.A[0] = A0; a.B[0] = B0; a.ldb[0] = 128; a.koff[0] = 0;
    a.A[1] = A1; a.B[1] = B1; a.ldb[1] = 128; a.koff[1] = 0;
    a.nTerms = 2; a.bias0 = bias0; a.bias1 = bias1;
    a.C = C; a.M = M; a.N = N; a.relu = 0;
    tc_launch(a);
}

static void tc3(const float* A0, const float* B0, int ldb0, int koff0, int nf0,
                const float* A1, const float* B1, int ldb1, int koff1, int nf1,
                const float* A2, const float* B2, int ldb2, int koff2, int nf2,
                const float* bias0, const float* bias1,
                float* C, int M, int N) {
    TcArgs a = {};
    a.A[0] = A0; a.B[0] = B0; a.ldb[0] = ldb0; a.koff[0] = koff0; a.negflip[0] = nf0;
    a.A[1] = A1; a.B[1] = B1; a.ldb[1] = ldb1; a.koff[1] = koff1; a.negflip[1] = nf1;
    a.A[2] = A2; a.B[2] = B2; a.ldb[2] = ldb2; a.koff[2] = koff2; a.negflip[2] = nf2;
    a.nTerms = 3; a.bias0 = bias0; a.bias1 = bias1;
    a.C = C; a.M = M; a.N = N; a.relu = 0;
    tc_launch(a);
}

extern "C" void kernel_launch(void* const* d_in, const int* in_sizes, int n_in,
                              void* d_out, int out_size) {
    const float* L_init_w = (const float*)d_in[0];
    const float* L_init_b = (const float*)d_in[1];
    const float* C_init_w = (const float*)d_in[2];
    const float* C_init_b = (const float*)d_in[3];
    const float* Lmsg_w   = (const float*)d_in[4];
    const float* Lmsg_b   = (const float*)d_in[5];
    const float* Cmsg_w   = (const float*)d_in[6];
    const float* Cmsg_b   = (const float*)d_in[7];
    const float* Cu_wih   = (const float*)d_in[8];
    const float* Cu_whh   = (const float*)d_in[9];
    const float* Cu_bih   = (const float*)d_in[10];
    const float* Cu_bhh   = (const float*)d_in[11];
    const float* Lu_wih   = (const float*)d_in[12];
    const float* Lu_whh   = (const float*)d_in[13];
    const float* Lu_bih   = (const float*)d_in[14];
    const float* Lu_bhh   = (const float*)d_in[15];
    const int*   esrc     = (const int*)d_in[16];
    const int*   edst     = (const int*)d_in[17];
    const int E = in_sizes[16];

    static int smem_set = 0;
    if (!smem_set) {
        cudaFuncSetAttribute(tc_gemm, cudaFuncAttributeMaxDynamicSharedMemorySize, SMEM_TC_BYTES);
        smem_set = 1;
    }

    float *h, *c, *msg, *t0, *t1, *gates;
    cudaGetSymbolAddress((void**)&h,     g_h);
    cudaGetSymbolAddress((void**)&c,     g_c);
    cudaGetSymbolAddress((void**)&msg,   g_msg);
    cudaGetSymbolAddress((void**)&t0,    g_t0);
    cudaGetSymbolAddress((void**)&t1,    g_t1);
    cudaGetSymbolAddress((void**)&gates, g_gates);
    (void)t1;

    init_kernel<<<NTOTAL, 128>>>(L_init_w, L_init_b, C_init_w, C_init_b, h);
    zero_kernel<<<((size_t)NTOTAL * 32 + 255) / 256, 256>>>((float4*)c, (size_t)NTOTAL * 32);

    dim3 sblk(32, 8);
    int sgrid = (E + 7) / 8;
    float* hC = h + (size_t)V2_ * D_;
    float* cC = c + (size_t)V2_ * D_;

    for (int r = 0; r < NROUNDS; ++r) {
        // literal -> clause messages: lm = MLP3(h_lit)
        tc1(h,  Lmsg_w,                 Lmsg_b,           t0, V2_, 128, 1);
        tc1(t0, Lmsg_w + 128 * 128,     Lmsg_b + 128,     msg, V2_, 128, 1);
        tc1(msg, Lmsg_w + 2 * 128 * 128, Lmsg_b + 2 * 128, t0, V2_, 128, 0);
        zero_kernel<<<((size_t)NCL * 32 + 255) / 256, 256>>>((float4*)msg, (size_t)NCL * 32);
        scatter_kernel<<<sgrid, sblk>>>(t0, esrc, edst, E, msg);

        // clause LSTM
        tc2(msg, Cu_wih, hC, Cu_whh, Cu_bih, Cu_bhh, gates, NCL, 512);
        lstm_kernel<<<((size_t)NCL * 32 + 255) / 256, 256>>>(gates, hC, cC, NCL);

        // clause -> literal messages: cm = MLP3(h_clause)
        tc1(hC, Cmsg_w,                 Cmsg_b,           t0, NCL, 128, 1);
        tc1(t0, Cmsg_w + 128 * 128,     Cmsg_b + 128,     t1, NCL, 128, 1);
        tc1(t1, Cmsg_w + 2 * 128 * 128, Cmsg_b + 2 * 128, t0, NCL, 128, 0);
        zero_kernel<<<((size_t)V2_ * 32 + 255) / 256, 256>>>((float4*)msg, (size_t)V2_ * 32);
        scatter_kernel<<<sgrid, sblk>>>(t0, edst, esrc, E, msg);

        // literal LSTM: x = [l_msg, l_neg] (neg via in-GEMM row flip)
        tc3(msg, Lu_wih, 256, 0,   0,
            h,   Lu_wih, 256, 128, 1,
            h,   Lu_whh, 128, 0,   0,
            Lu_bih, Lu_bhh, gates, V2_, 512);
        lstm_kernel<<<((size_t)V2_ * 32 + 255) / 256, 256>>>(gates, h, c, V2_);
    }

    copy_kernel<<<((size_t)NTOTAL * 32 + 255) / 256, 256>>>(
        (const float4*)h, (float4*)d_out, (size_t)NTOTAL * 32);
}

// round 8
// speedup vs baseline: 2.1614x; 2.1614x over previous
#include <cuda_runtime.h>
#include <cuda_bf16.h>
#include <cstdint>

#define D_      128
#define NVARS   50000
#define V2_     100000
#define NCL     200000
#define NTOTAL  300000
#define NROUNDS 16

// ---------------- persistent scratch ---------------------------------------
__device__ float g_h[(size_t)NTOTAL * D_];
__device__ float g_c[(size_t)NTOTAL * D_];
__device__ float g_msg[(size_t)NCL * D_];
__device__ float g_t0[(size_t)NCL * D_];
__device__ float g_gates[(size_t)NCL * 4 * D_];

// bf16 hi/lo mirrors (u32 = packed bf16x2, 64 u32 per 128-float row)
__device__ uint32_t g_hhi[(size_t)NTOTAL * 64];
__device__ uint32_t g_hlo[(size_t)NTOTAL * 64];
__device__ uint32_t g_mhi[(size_t)NCL * 64];
__device__ uint32_t g_mlo[(size_t)NCL * 64];
__device__ uint32_t g_i1hi[(size_t)NCL * 64];
__device__ uint32_t g_i1lo[(size_t)NCL * 64];
__device__ uint32_t g_i2hi[(size_t)NCL * 64];
__device__ uint32_t g_i2lo[(size_t)NCL * 64];
// weights: Lmsg(24576) Cmsg(24576) CuWih(32768) CuWhh(32768) LuWih(65536) LuWhh(32768)
#define WO_LMSG  0
#define WO_CMSG  24576
#define WO_CWIH  49152
#define WO_CWHH  81920
#define WO_LWIH  114688
#define WO_LWHH  180224
#define W_TOTAL  212992
__device__ uint32_t g_whi[W_TOTAL];
__device__ uint32_t g_wlo[W_TOTAL];

// ---------------- helpers ---------------------------------------------------
__device__ __forceinline__ void cvt2(float x, float y, uint32_t& hi, uint32_t& lo) {
    __nv_bfloat16 hx = __float2bfloat16_rn(x);
    __nv_bfloat16 hy = __float2bfloat16_rn(y);
    __nv_bfloat162 hp = __halves2bfloat162(hx, hy);
    hi = *(uint32_t*)&hp;
    __nv_bfloat16 lx = __float2bfloat16_rn(x - __bfloat162float(hx));
    __nv_bfloat16 ly = __float2bfloat16_rn(y - __bfloat162float(hy));
    __nv_bfloat162 lp = __halves2bfloat162(lx, ly);
    lo = *(uint32_t*)&lp;
}

__device__ __forceinline__ void mma_bf16(float* d, const uint32_t* a, uint32_t b0, uint32_t b1) {
    asm volatile(
        "mma.sync.aligned.m16n8k16.row.col.f32.bf16.bf16.f32 "
        "{%0,%1,%2,%3}, {%4,%5,%6,%7}, {%8,%9}, {%0,%1,%2,%3};\n"
        : "+f"(d[0]), "+f"(d[1]), "+f"(d[2]), "+f"(d[3])
        : "r"(a[0]), "r"(a[1]), "r"(a[2]), "r"(a[3]), "r"(b0), "r"(b1));
}

__device__ __forceinline__ uint32_t smem_u32(const void* p) {
    uint32_t a;
    asm("{ .reg .u64 t; cvta.to.shared.u64 t, %1; cvt.u32.u64 %0, t; }" : "=r"(a) : "l"(p));
    return a;
}

__device__ __forceinline__ void cp16(uint32_t saddr, const void* g, bool pred) {
    int sz = pred ? 16 : 0;
    asm volatile("cp.async.cg.shared.global [%0], [%1], 16, %2;"
                 :: "r"(saddr), "l"(g), "r"(sz));
}

// ---------------- GEMM (mma.sync bf16 3-pass, cp.async 2-stage pipeline) ----
// C[M, bcol:bcol+128] = sum_t A_t[M,0:128] @ B_t[:, bkoff:bkoff+128]^T + bias
#define ASTR 36
#define STAGE_U32 (4 * 128 * ASTR)            // 18432 u32 per stage
#define SMEM_TC_BYTES (2 * STAGE_U32 * 4)     // 147456 B

struct TcArgs {
    const uint32_t *Ahi[3], *Alo[3];
    int negflip[3];
    const uint32_t *Bhi[3], *Blo[3];
    int ldb32[3], bko32[3];
    int nTerms;
    const float *bias0, *bias1;
    float* C;            // fp32 out (optional)
    uint32_t *Chi, *Clo; // bf16 hi/lo out (optional)
    int M, N;
    int relu;
};

__device__ __forceinline__ void fill_stage(const TcArgs& a, int s, uint32_t sbase,
                                           int brow, int bcol, int tid) {
    const int term = s >> 1, kh = s & 1, b = s & 1;
    const uint32_t st = sbase + (uint32_t)b * (STAGE_U32 * 4);
    const uint32_t* gah = a.Ahi[term];
    const uint32_t* gal = a.Alo[term];
    const int nflip = a.negflip[term];
#pragma unroll
    for (int i = 0; i < 4; ++i) {
        int f = i * 256 + tid;
        int r = f >> 3, cch = f & 7;
        int gr = brow + r;
        bool p = gr < a.M;
        int src = p ? gr : 0;
        if (nflip) src = (src < NVARS) ? src + NVARS : src - NVARS;
        size_t go = (size_t)src * 64 + kh * 32 + cch * 4;
        uint32_t so = st + (uint32_t)(r * ASTR + cch * 4) * 4;
        cp16(so, gah + go, p);
        cp16(so + 4608u * 4, gal + go, p);
    }
    const uint32_t* gbh = a.Bhi[term];
    const uint32_t* gbl = a.Blo[term];
    const int ldb = a.ldb32[term], bko = a.bko32[term];
#pragma unroll
    for (int i = 0; i < 4; ++i) {
        int f = i * 256 + tid;
        int r = f >> 3, cch = f & 7;
        size_t go = (size_t)(bcol + r) * ldb + bko + kh * 32 + cch * 4;
        uint32_t so = st + (uint32_t)(2 * 4608 + r * ASTR + cch * 4) * 4;
        cp16(so, gbh + go, true);
        cp16(so + 4608u * 4, gbl + go, true);
    }
    asm volatile("cp.async.commit_group;" ::: "memory");
}

__global__ __launch_bounds__(256) void tc_gemm(TcArgs a) {
    extern __shared__ uint32_t sm[];
    const uint32_t sbase = smem_u32(sm);
    const int tid  = threadIdx.x;
    const int wid  = tid >> 5;
    const int lane = tid & 31;
    const int g    = lane >> 2;
    const int t    = lane & 3;
    const int wm   = (wid >> 1) * 32;
    const int wn   = (wid & 1) * 64;
    const int brow = blockIdx.x << 7;
    const int bcol = blockIdx.y << 7;

    float acc[2][8][4];
#pragma unroll
    for (int mf = 0; mf < 2; ++mf)
#pragma unroll
        for (int nf = 0; nf < 8; ++nf)
#pragma unroll
            for (int k = 0; k < 4; ++k) acc[mf][nf][k] = 0.f;

    const int nst = a.nTerms * 2;
    fill_stage(a, 0, sbase, brow, bcol, tid);
    fill_stage(a, 1, sbase, brow, bcol, tid);

    for (int s = 0; s < nst; ++s) {
        const int b = s & 1;
        if (s + 1 < nst) asm volatile("cp.async.wait_group 1;" ::: "memory");
        else             asm volatile("cp.async.wait_group 0;" ::: "memory");
        __syncthreads();

        uint32_t* st = sm + b * STAGE_U32;
        uint32_t* SAh = st;
        uint32_t* SAl = st + 4608;
        uint32_t* SBh = st + 2 * 4608;
        uint32_t* SBl = st + 3 * 4608;
#pragma unroll
        for (int ks = 0; ks < 4; ++ks) {
            const int c0 = ks * 8 + t;
            uint32_t ah[2][4], al[2][4];
#pragma unroll
            for (int mf = 0; mf < 2; ++mf) {
                const int r = wm + mf * 16 + g;
                const uint32_t* p = SAh + r * ASTR + c0;
                ah[mf][0] = p[0]; ah[mf][1] = p[8 * ASTR];
                ah[mf][2] = p[4]; ah[mf][3] = p[8 * ASTR + 4];
                const uint32_t* q = SAl + r * ASTR + c0;
                al[mf][0] = q[0]; al[mf][1] = q[8 * ASTR];
                al[mf][2] = q[4]; al[mf][3] = q[8 * ASTR + 4];
            }
#pragma unroll
            for (int nf = 0; nf < 8; ++nf) {
                const int nr = wn + nf * 8 + g;
                const uint32_t* pb = SBh + nr * ASTR + c0;
                uint32_t bh0 = pb[0], bh1 = pb[4];
                const uint32_t* qb = SBl + nr * ASTR + c0;
                uint32_t bl0 = qb[0], bl1 = qb[4];
#pragma unroll
                for (int mf = 0; mf < 2; ++mf) {
                    mma_bf16(acc[mf][nf], ah[mf], bh0, bh1);
                    mma_bf16(acc[mf][nf], ah[mf], bl0, bl1);
                    mma_bf16(acc[mf][nf], al[mf], bh0, bh1);
                }
            }
        }
        __syncthreads();
        if (s + 2 < nst) fill_stage(a, s + 2, sbase, brow, bcol, tid);
    }

    // ---- epilogue ----
#pragma unroll
    for (int nf = 0; nf < 8; ++nf) {
        const int col = bcol + wn + nf * 8 + 2 * t;
        float b0v = a.bias0[col], b1v = a.bias0[col + 1];
        if (a.bias1) { b0v += a.bias1[col]; b1v += a.bias1[col + 1]; }
#pragma unroll
        for (int mf = 0; mf < 2; ++mf) {
            const int row = brow + wm + mf * 16 + g;
            float x0 = acc[mf][nf][0] + b0v;
            float x1 = acc[mf][nf][1] + b1v;
            float x2 = acc[mf][nf][2] + b0v;
            float x3 = acc[mf][nf][3] + b1v;
            if (a.relu) {
                x0 = fmaxf(x0, 0.f); x1 = fmaxf(x1, 0.f);
                x2 = fmaxf(x2, 0.f); x3 = fmaxf(x3, 0.f);
            }
            if (a.C) {
                if (row < a.M)
                    *(float2*)(a.C + (size_t)row * a.N + col) = make_float2(x0, x1);
                if (row + 8 < a.M)
                    *(float2*)(a.C + (size_t)(row + 8) * a.N + col) = make_float2(x2, x3);
            }
            if (a.Chi) {
                uint32_t hv, lv;
                if (row < a.M) {
                    cvt2(x0, x1, hv, lv);
                    a.Chi[(size_t)row * 64 + (col >> 1)] = hv;
                    a.Clo[(size_t)row * 64 + (col >> 1)] = lv;
                }
                if (row + 8 < a.M) {
                    cvt2(x2, x3, hv, lv);
                    a.Chi[(size_t)(row + 8) * 64 + (col >> 1)] = hv;
                    a.Clo[(size_t)(row + 8) * 64 + (col >> 1)] = lv;
                }
            }
        }
    }
}

// ---------------- edge scatter-add -----------------------------------------
__global__ void scatter_kernel(const float* __restrict__ rows,
                               const int* __restrict__ gidx,
                               const int* __restrict__ sidx,
                               int E, float* __restrict__ out) {
    int e = blockIdx.x * 8 + threadIdx.y;
    if (e >= E) return;
    int s = gidx[e];
    int d = sidx[e];
    float4 v = *(const float4*)(rows + (size_t)s * D_ + threadIdx.x * 4);
    float* p = out + (size_t)d * D_ + threadIdx.x * 4;
    asm volatile("red.global.add.v4.f32 [%0], {%1, %2, %3, %4};"
                 :: "l"(p), "f"(v.x), "f"(v.y), "f"(v.z), "f"(v.w)
                 : "memory");
}

// ---------------- elementwise ----------------------------------------------
__device__ __forceinline__ float sigf(float x) { return 1.f / (1.f + expf(-x)); }

__global__ void lstm_kernel(const float* __restrict__ gates,
                            float* __restrict__ h, float* __restrict__ c,
                            uint32_t* __restrict__ hhi, uint32_t* __restrict__ hlo,
                            int M) {
    size_t idx = (size_t)blockIdx.x * blockDim.x + threadIdx.x;
    if (idx >= (size_t)M * 32) return;
    size_t r = idx >> 5;
    int q = (int)(idx & 31) * 4;
    const float* gb = gates + r * 512;
    float4 gi = *(const float4*)(gb + q);
    float4 gf = *(const float4*)(gb + 128 + q);
    float4 gg = *(const float4*)(gb + 256 + q);
    float4 go = *(const float4*)(gb + 384 + q);
    float4 cc = *(const float4*)(c + r * D_ + q);
    float4 c2, hh;
    c2.x = sigf(gf.x) * cc.x + sigf(gi.x) * tanhf(gg.x); hh.x = sigf(go.x) * tanhf(c2.x);
    c2.y = sigf(gf.y) * cc.y + sigf(gi.y) * tanhf(gg.y); hh.y = sigf(go.y) * tanhf(c2.y);
    c2.z = sigf(gf.z) * cc.z + sigf(gi.z) * tanhf(gg.z); hh.z = sigf(go.z) * tanhf(c2.z);
    c2.w = sigf(gf.w) * cc.w + sigf(gi.w) * tanhf(gg.w); hh.w = sigf(go.w) * tanhf(c2.w);
    *(float4*)(c + r * D_ + q) = c2;
    *(float4*)(h + r * D_ + q) = hh;
    uint32_t h0, l0, h1, l1;
    cvt2(hh.x, hh.y, h0, l0);
    cvt2(hh.z, hh.w, h1, l1);
    *(uint2*)(hhi + r * 64 + (q >> 1)) = make_uint2(h0, h1);
    *(uint2*)(hlo + r * 64 + (q >> 1)) = make_uint2(l0, l1);
}

__global__ void init_kernel(const float* __restrict__ lw, const float* __restrict__ lb,
                            const float* __restrict__ cw, const float* __restrict__ cb,
                            float* __restrict__ h,
                            uint32_t* __restrict__ hhi, uint32_t* __restrict__ hlo) {
    int tid = threadIdx.x;           // 0..63
    size_t row = blockIdx.x;
    int d0 = tid * 2;
    float v0, v1;
    if (row < V2_) { v0 = lw[d0] + lb[d0]; v1 = lw[d0 + 1] + lb[d0 + 1]; }
    else           { v0 = cw[d0] + cb[d0]; v1 = cw[d0 + 1] + cb[d0 + 1]; }
    h[row * D_ + d0] = v0;
    h[row * D_ + d0 + 1] = v1;
    uint32_t hv, lv;
    cvt2(v0, v1, hv, lv);
    hhi[row * 64 + tid] = hv;
    hlo[row * 64 + tid] = lv;
}

__global__ void cvt_pairs(const float2* __restrict__ src,
                          uint32_t* __restrict__ hi, uint32_t* __restrict__ lo, size_t n) {
    size_t i = (size_t)blockIdx.x * blockDim.x + threadIdx.x;
    if (i >= n) return;
    float2 v = src[i];
    uint32_t hv, lv;
    cvt2(v.x, v.y, hv, lv);
    hi[i] = hv; lo[i] = lv;
}

__global__ void zero_kernel(float4* __restrict__ p, size_t n4) {
    size_t i = (size_t)blockIdx.x * blockDim.x + threadIdx.x;
    if (i < n4) p[i] = make_float4(0.f, 0.f, 0.f, 0.f);
}

__global__ void copy_kernel(const float4* __restrict__ src, float4* __restrict__ dst, size_t n4) {
    size_t i = (size_t)blockIdx.x * blockDim.x + threadIdx.x;
    if (i < n4) dst[i] = src[i];
}

// ---------------- host wrappers --------------------------------------------
static void tc_launch(TcArgs& a) {
    dim3 grid((a.M + 127) >> 7, a.N >> 7);
    tc_gemm<<<grid, 256, SMEM_TC_BYTES>>>(a);
}

extern "C" void kernel_launch(void* const* d_in, const int* in_sizes, int n_in,
                              void* d_out, int out_size) {
    const float* L_init_w = (const float*)d_in[0];
    const float* L_init_b = (const float*)d_in[1];
    const float* C_init_w = (const float*)d_in[2];
    const float* C_init_b = (const float*)d_in[3];
    const float* Lmsg_w   = (const float*)d_in[4];
    const float* Lmsg_b   = (const float*)d_in[5];
    const float* Cmsg_w   = (const float*)d_in[6];
    const float* Cmsg_b   = (const float*)d_in[7];
    const float* Cu_wih   = (const float*)d_in[8];
    const float* Cu_whh   = (const float*)d_in[9];
    const float* Cu_bih   = (const float*)d_in[10];
    const float* Cu_bhh   = (const float*)d_in[11];
    const float* Lu_wih   = (const float*)d_in[12];
    const float* Lu_whh   = (const float*)d_in[13];
    const float* Lu_bih   = (const float*)d_in[14];
    const float* Lu_bhh   = (const float*)d_in[15];
    const int*   esrc     = (const int*)d_in[16];
    const int*   edst     = (const int*)d_in[17];
    const int E = in_sizes[16];

    static int smem_set = 0;
    if (!smem_set) {
        cudaFuncSetAttribute(tc_gemm, cudaFuncAttributeMaxDynamicSharedMemorySize, SMEM_TC_BYTES);
        smem_set = 1;
    }

    float *h, *c, *msg, *t0, *gates;
    uint32_t *hhi, *hlo, *mhi, *mlo, *i1hi, *i1lo, *i2hi, *i2lo, *whi, *wlo;
    cudaGetSymbolAddress((void**)&h,     g_h);
    cudaGetSymbolAddress((void**)&c,     g_c);
    cudaGetSymbolAddress((void**)&msg,   g_msg);
    cudaGetSymbolAddress((void**)&t0,    g_t0);
    cudaGetSymbolAddress((void**)&gates, g_gates);
    cudaGetSymbolAddress((void**)&hhi,   g_hhi);
    cudaGetSymbolAddress((void**)&hlo,   g_hlo);
    cudaGetSymbolAddress((void**)&mhi,   g_mhi);
    cudaGetSymbolAddress((void**)&mlo,   g_mlo);
    cudaGetSymbolAddress((void**)&i1hi,  g_i1hi);
    cudaGetSymbolAddress((void**)&i1lo,  g_i1lo);
    cudaGetSymbolAddress((void**)&i2hi,  g_i2hi);
    cudaGetSymbolAddress((void**)&i2lo,  g_i2lo);
    cudaGetSymbolAddress((void**)&whi,   g_whi);
    cudaGetSymbolAddress((void**)&wlo,   g_wlo);

    // ---- pre-convert weights (cheap, once per launch) ----
    cvt_pairs<<<(24576 + 255) / 256, 256>>>((const float2*)Lmsg_w, whi + WO_LMSG, wlo + WO_LMSG, 24576);
    cvt_pairs<<<(24576 + 255) / 256, 256>>>((const float2*)Cmsg_w, whi + WO_CMSG, wlo + WO_CMSG, 24576);
    cvt_pairs<<<(32768 + 255) / 256, 256>>>((const float2*)Cu_wih, whi + WO_CWIH, wlo + WO_CWIH, 32768);
    cvt_pairs<<<(32768 + 255) / 256, 256>>>((const float2*)Cu_whh, whi + WO_CWHH, wlo + WO_CWHH, 32768);
    cvt_pairs<<<(65536 + 255) / 256, 256>>>((const float2*)Lu_wih, whi + WO_LWIH, wlo + WO_LWIH, 65536);
    cvt_pairs<<<(32768 + 255) / 256, 256>>>((const float2*)Lu_whh, whi + WO_LWHH, wlo + WO_LWHH, 32768);

    init_kernel<<<NTOTAL, 64>>>(L_init_w, L_init_b, C_init_w, C_init_b, h, hhi, hlo);
    zero_kernel<<<((size_t)NTOTAL * 32 + 255) / 256, 256>>>((float4*)c, (size_t)NTOTAL * 32);

    dim3 sblk(32, 8);
    int sgrid = (E + 7) / 8;

    for (int r = 0; r < NROUNDS; ++r) {
        TcArgs a;

        // ---- L-MLP layer 1: A=h(lit) -> i1 (hi/lo only) ----
        a = {};
        a.Ahi[0] = hhi; a.Alo[0] = hlo;
        a.Bhi[0] = whi + WO_LMSG; a.Blo[0] = wlo + WO_LMSG; a.ldb32[0] = 64;
        a.nTerms = 1; a.bias0 = Lmsg_b; a.Chi = i1hi; a.Clo = i1lo;
        a.M = V2_; a.N = 128; a.relu = 1;
        tc_launch(a);
        // layer 2: i1 -> i2
        a.Ahi[0] = i1hi; a.Alo[0] = i1lo;
        a.Bhi[0] = whi + WO_LMSG + 8192; a.Blo[0] = wlo + WO_LMSG + 8192;
        a.bias0 = Lmsg_b + 128; a.Chi = i2hi; a.Clo = i2lo;
        tc_launch(a);
        // layer 3: i2 -> t0 (fp32)
        a.Ahi[0] = i2hi; a.Alo[0] = i2lo;
        a.Bhi[0] = whi + WO_LMSG + 16384; a.Blo[0] = wlo + WO_LMSG + 16384;
        a.bias0 = Lmsg_b + 256; a.Chi = nullptr; a.Clo = nullptr;
        a.C = t0; a.relu = 0;
        tc_launch(a);

        zero_kernel<<<((size_t)NCL * 32 + 255) / 256, 256>>>((float4*)msg, (size_t)NCL * 32);
        scatter_kernel<<<sgrid, sblk>>>(t0, esrc, edst, E, msg);
        cvt_pairs<<<((size_t)NCL * 64 + 255) / 256, 256>>>((const float2*)msg, mhi, mlo, (size_t)NCL * 64);

        // ---- clause gates: msg@CuWih^T + hC@CuWhh^T ----
        a = {};
        a.Ahi[0] = mhi; a.Alo[0] = mlo;
        a.Bhi[0] = whi + WO_CWIH; a.Blo[0] = wlo + WO_CWIH; a.ldb32[0] = 64;
        a.Ahi[1] = hhi + (size_t)V2_ * 64; a.Alo[1] = hlo + (size_t)V2_ * 64;
        a.Bhi[1] = whi + WO_CWHH; a.Blo[1] = wlo + WO_CWHH; a.ldb32[1] = 64;
        a.nTerms = 2; a.bias0 = Cu_bih; a.bias1 = Cu_bhh;
        a.C = gates; a.M = NCL; a.N = 512;
        tc_launch(a);
        lstm_kernel<<<((size_t)NCL * 32 + 255) / 256, 256>>>(
            gates, h + (size_t)V2_ * D_, c + (size_t)V2_ * D_,
            hhi + (size_t)V2_ * 64, hlo + (size_t)V2_ * 64, NCL);

        // ---- C-MLP ----
        a = {};
        a.Ahi[0] = hhi + (size_t)V2_ * 64; a.Alo[0] = hlo + (size_t)V2_ * 64;
        a.Bhi[0] = whi + WO_CMSG; a.Blo[0] = wlo + WO_CMSG; a.ldb32[0] = 64;
        a.nTerms = 1; a.bias0 = Cmsg_b; a.Chi = i1hi; a.Clo = i1lo;
        a.M = NCL; a.N = 128; a.relu = 1;
        tc_launch(a);
        a.Ahi[0] = i1hi; a.Alo[0] = i1lo;
        a.Bhi[0] = whi + WO_CMSG + 8192; a.Blo[0] = wlo + WO_CMSG + 8192;
        a.bias0 = Cmsg_b + 128; a.Chi = i2hi; a.Clo = i2lo;
        tc_launch(a);
        a.Ahi[0] = i2hi; a.Alo[0] = i2lo;
        a.Bhi[0] = whi + WO_CMSG + 16384; a.Blo[0] = wlo + WO_CMSG + 16384;
        a.bias0 = Cmsg_b + 256; a.Chi = nullptr; a.Clo = nullptr;
        a.C = t0; a.relu = 0;
        tc_launch(a);

        zero_kernel<<<((size_t)V2_ * 32 + 255) / 256, 256>>>((float4*)msg, (size_t)V2_ * 32);
        scatter_kernel<<<sgrid, sblk>>>(t0, edst, esrc, E, msg);
        cvt_pairs<<<((size_t)V2_ * 64 + 255) / 256, 256>>>((const float2*)msg, mhi, mlo, (size_t)V2_ * 64);

        // ---- literal gates: msg@LuWih[:, :128]^T + hneg@LuWih[:, 128:]^T + h@LuWhh^T ----
        a = {};
        a.Ahi[0] = mhi; a.Alo[0] = mlo;
        a.Bhi[0] = whi + WO_LWIH; a.Blo[0] = wlo + WO_LWIH; a.ldb32[0] = 128; a.bko32[0] = 0;
        a.Ahi[1] = hhi; a.Alo[1] = hlo; a.negflip[1] = 1;
        a.Bhi[1] = whi + WO_LWIH; a.Blo[1] = wlo + WO_LWIH; a.ldb32[1] = 128; a.bko32[1] = 64;
        a.Ahi[2] = hhi; a.Alo[2] = hlo;
        a.Bhi[2] = whi + WO_LWHH; a.Blo[2] = wlo + WO_LWHH; a.ldb32[2] = 64;
        a.nTerms = 3; a.bias0 = Lu_bih; a.bias1 = Lu_bhh;
        a.C = gates; a.M = V2_; a.N = 512;
        tc_launch(a);
        lstm_kernel<<<((size_t)V2_ * 32 + 255) / 256, 256>>>(gates, h, c, hhi, hlo, V2_);
    }

    copy_kernel<<<((size_t)NTOTAL * 32 + 255) / 256, 256>>>(
        (const float4*)h, (float4*)d_out, (size_t)NTOTAL * 32);
}